// round 8
// baseline (speedup 1.0000x reference)
#include <cuda_runtime.h>
#include <math.h>

#define Bb 4
#define Tt 128
#define Uu 64
#define Dd 512
#define Hh 640
#define Vv 1024
#define UB 32   // (t,u)-rows per CTA in joiner kernel

#define JOINER_SMEM (2 * UB * Hh * (int)sizeof(float))   // 163840 B

// Packed fp32x2 FMA (sm_100+): d.lo += a.lo*b.lo, d.hi += a.hi*b.hi (exact fp32)
#define FMA2(acc, a, b) \
    asm("fma.rn.f32x2 %0, %1, %2, %0;" : "+l"(acc) : "l"(a), "l"(b))

// Scratch (no allocations allowed): projected source / target activations.
// g_ps includes the b1 bias.
__device__ float g_ps[Bb * Tt * Hh];   // (B*T, H)
__device__ float g_pt[Bb * Uu * Hh];   // (B*U, H)

// ---------------------------------------------------------------------------
// Kernel A: ps = src @ W1[0:D] + b1   (rows 0..511)
//           pt = tgt @ W1[D:2D]       (rows 512..767)
// 8 rows per CTA, 256 threads, input rows staged in smem, W1 column-coalesced.
// ---------------------------------------------------------------------------
__global__ __launch_bounds__(256) void proj_kernel(
    const float* __restrict__ src, const float* __restrict__ tgt,
    const float* __restrict__ W1, const float* __restrict__ b1) {
    __shared__ float s_in[8 * Dd];   // 16 KB

    const int row0 = blockIdx.x * 8;
    const bool is_src = (row0 < Bb * Tt);
    const float* inp = is_src ? (src + (size_t)row0 * Dd)
                              : (tgt + (size_t)(row0 - Bb * Tt) * Dd);
    const float* w = W1 + (is_src ? 0 : (size_t)Dd * Hh);
    float* outp = is_src ? (g_ps + (size_t)row0 * Hh)
                         : (g_pt + (size_t)(row0 - Bb * Tt) * Hh);

    const int tid = threadIdx.x;
    for (int idx = tid; idx < 8 * Dd; idx += 256) s_in[idx] = inp[idx];
    __syncthreads();

    const int c0 = tid;           // always < 640
    const int c1 = tid + 256;     // always < 640
    const int c2 = tid + 512;     // valid only if tid < 128
    const bool has2 = (tid < 128);

    float acc[8][3];
#pragma unroll
    for (int r = 0; r < 8; r++) {
        acc[r][0] = 0.f; acc[r][1] = 0.f; acc[r][2] = 0.f;
    }

#pragma unroll 4
    for (int d = 0; d < Dd; d++) {
        const float* wr = w + (size_t)d * Hh;
        float w0 = wr[c0];
        float w1v = wr[c1];
        float w2v = has2 ? wr[c2] : 0.f;
#pragma unroll
        for (int r = 0; r < 8; r++) {
            float sv = s_in[r * Dd + d];
            acc[r][0] = fmaf(sv, w0, acc[r][0]);
            acc[r][1] = fmaf(sv, w1v, acc[r][1]);
            acc[r][2] = fmaf(sv, w2v, acc[r][2]);
        }
    }

    float bb0 = is_src ? b1[c0] : 0.f;
    float bb1 = is_src ? b1[c1] : 0.f;
    float bb2 = (is_src && has2) ? b1[c2] : 0.f;
#pragma unroll
    for (int r = 0; r < 8; r++) {
        outp[(size_t)r * Hh + c0] = acc[r][0] + bb0;
        outp[(size_t)r * Hh + c1] = acc[r][1] + bb1;
        if (has2) outp[(size_t)r * Hh + c2] = acc[r][2] + bb2;
    }
}

// ---------------------------------------------------------------------------
// Kernel B: for a block of 32 (t,u) rows:
//   h = tanh(ps[b,t,:] + pt[b,u,:])      stored DUPLICATED {v,v} in smem
//   logits = h @ W2 + b2                 via packed fma.rn.f32x2 (FFMA2)
//   out = log_softmax(logits)            fused, smem reduce
// 512 threads: rg = tid>>7 (0..3) selects 8 rows, cg = tid&127 selects 8 cols.
// 32-row tile halves W2 L2 re-read traffic vs 16-row tile.
// ---------------------------------------------------------------------------
__global__ __launch_bounds__(512, 1) void joiner_kernel(
    const float* __restrict__ W2, const float* __restrict__ b2,
    float* __restrict__ out) {
    extern __shared__ float sh2[];   // [UB*Hh] float2 (duplicated h); 160 KB
    __shared__ float rowstat[UB];

    const int bx = blockIdx.x;
    const int ub = bx & 1;               // U/UB = 2 blocks
    const int t  = (bx >> 1) & (Tt - 1);
    const int b  = bx >> 8;              // 2*128 = 256 CTAs per batch
    const int u0 = ub * UB;
    const int tid = threadIdx.x;

    // Build duplicated h tile: one LDS.64 later yields packed broadcast {v,v}
    const float* psr = g_ps + ((size_t)(b * Tt + t)) * Hh;
    const float* ptb = g_pt + ((size_t)(b * Uu + u0)) * Hh;
    for (int idx = tid; idx < UB * Hh; idx += 512) {
        int r = idx / Hh;
        int k = idx - r * Hh;
        float v = tanhf(psr[k] + ptb[(size_t)r * Hh + k]);
        ((float2*)sh2)[idx] = make_float2(v, v);
    }
    __syncthreads();

    const int rg = tid >> 7;         // 0..3
    const int cg = tid & 127;        // 0..127
    const int c0 = cg * 8;
    const int r0 = rg * 8;

    unsigned long long acc2[8][4];   // 8 rows x 4 col-pairs (cols c0..c0+7)
#pragma unroll
    for (int r = 0; r < 8; r++)
#pragma unroll
        for (int j = 0; j < 4; j++) acc2[r][j] = 0ull;  // (0.0f, 0.0f)

    const unsigned long long* hrow =
        (const unsigned long long*)sh2 + (size_t)r0 * Hh;  // u64 index = r*Hh + k
    const float* w2p = W2 + c0;

#pragma unroll 2
    for (int k = 0; k < Hh; k++) {
        const float* wk = w2p + (size_t)k * Vv;
        ulonglong2 wA = *(const ulonglong2*)wk;        // cols (0,1),(2,3)
        ulonglong2 wB = *(const ulonglong2*)(wk + 4);  // cols (4,5),(6,7)
#pragma unroll
        for (int r = 0; r < 8; r++) {
            unsigned long long hv = hrow[r * Hh + k];  // {h, h} broadcast
            FMA2(acc2[r][0], hv, wA.x);
            FMA2(acc2[r][1], hv, wA.y);
            FMA2(acc2[r][2], hv, wB.x);
            FMA2(acc2[r][3], hv, wB.y);
        }
    }

    // Unpack packed accumulators -> scalar acc[8][8]
    float acc[8][8];
#pragma unroll
    for (int r = 0; r < 8; r++)
#pragma unroll
        for (int j = 0; j < 4; j++) {
            unsigned long long v = acc2[r][j];
            acc[r][2 * j]     = __uint_as_float((unsigned int)v);
            acc[r][2 * j + 1] = __uint_as_float((unsigned int)(v >> 32));
        }

    // Bias
    float4 ba  = *(const float4*)(b2 + c0);
    float4 bbv = *(const float4*)(b2 + c0 + 4);
#pragma unroll
    for (int r = 0; r < 8; r++) {
        acc[r][0] += ba.x;  acc[r][1] += ba.y;
        acc[r][2] += ba.z;  acc[r][3] += ba.w;
        acc[r][4] += bbv.x; acc[r][5] += bbv.y;
        acc[r][6] += bbv.z; acc[r][7] += bbv.w;
    }

    __syncthreads();          // done reading sh2 as h-tile; reuse as red buffer
    float* red = sh2;         // [UB][128]

    // --- row max ---
#pragma unroll
    for (int r = 0; r < 8; r++) {
        float m = acc[r][0];
#pragma unroll
        for (int c = 1; c < 8; c++) m = fmaxf(m, acc[r][c]);
        red[(r0 + r) * 128 + cg] = m;
    }
    __syncthreads();
    if (tid < UB) {
        float m = -INFINITY;
        for (int i = 0; i < 128; i++) m = fmaxf(m, red[tid * 128 + i]);
        rowstat[tid] = m;
    }
    __syncthreads();
    float rmax[8];
#pragma unroll
    for (int r = 0; r < 8; r++) rmax[r] = rowstat[r0 + r];
    __syncthreads();

    // --- row sum(exp) ---
#pragma unroll
    for (int r = 0; r < 8; r++) {
        float s = 0.f;
#pragma unroll
        for (int c = 0; c < 8; c++) s += expf(acc[r][c] - rmax[r]);
        red[(r0 + r) * 128 + cg] = s;
    }
    __syncthreads();
    if (tid < UB) {
        float s = 0.f;
        for (int i = 0; i < 128; i++) s += red[tid * 128 + i];
        rowstat[tid] = rowstat[tid] + logf(s);   // max + log(sumexp)
    }
    __syncthreads();
    float rsub[8];
#pragma unroll
    for (int r = 0; r < 8; r++) rsub[r] = rowstat[r0 + r];

    // --- write log-probs ---
    size_t base = (((size_t)(b * Tt + t)) * Uu + (u0 + r0)) * Vv + c0;
#pragma unroll
    for (int r = 0; r < 8; r++) {
        float4 oa, ob;
        oa.x = acc[r][0] - rsub[r]; oa.y = acc[r][1] - rsub[r];
        oa.z = acc[r][2] - rsub[r]; oa.w = acc[r][3] - rsub[r];
        ob.x = acc[r][4] - rsub[r]; ob.y = acc[r][5] - rsub[r];
        ob.z = acc[r][6] - rsub[r]; ob.w = acc[r][7] - rsub[r];
        *(float4*)(out + base + (size_t)r * Vv)     = oa;
        *(float4*)(out + base + (size_t)r * Vv + 4) = ob;
    }
}

// ---------------------------------------------------------------------------
// Tail: reference returns (log_probs, source_lengths, target_lengths); if the
// flattened output carries the 8 length ints (as output-dtype floats), append
// them numerically cast.
// ---------------------------------------------------------------------------
__global__ void tail_kernel(const int* __restrict__ sl, const int* __restrict__ tl,
                            float* __restrict__ out, long long base, int tail) {
    int i = threadIdx.x;
    if (i < tail && i < 8) {
        out[base + i] = (i < 4) ? (float)sl[i] : (float)tl[i - 4];
    }
}

extern "C" void kernel_launch(void* const* d_in, const int* in_sizes, int n_in,
                              void* d_out, int out_size) {
    const float* src = (const float*)d_in[0];
    const int*   sl  = (const int*)d_in[1];
    const float* tgt = (const float*)d_in[2];
    const int*   tl  = (const int*)d_in[3];
    const float* W1  = (const float*)d_in[4];
    const float* b1  = (const float*)d_in[5];
    const float* W2  = (const float*)d_in[6];
    const float* b2  = (const float*)d_in[7];
    float* out = (float*)d_out;

    // Opt in to 160 KB dynamic smem for the joiner. Unconditional on every
    // call: idempotent, deterministic, host-side (not a captured stream op).
    cudaFuncSetAttribute(joiner_kernel,
                         cudaFuncAttributeMaxDynamicSharedMemorySize,
                         JOINER_SMEM);

    // 512 src rows + 256 tgt rows, 8 rows per CTA
    proj_kernel<<<(Bb * Tt + Bb * Uu) / 8, 256>>>(src, tgt, W1, b1);

    // 4 * 128 * (64/32) = 1024 CTAs
    joiner_kernel<<<Bb * Tt * (Uu / UB), 512, JOINER_SMEM>>>(W2, b2, out);

    long long mainN = (long long)Bb * Tt * Uu * Vv;   // 33554432
    long long tail = (long long)out_size - mainN;
    if (tail > 0) {
        tail_kernel<<<1, 32>>>(sl, tl, out, mainN, (int)tail);
    }
}

// round 11
// speedup vs baseline: 2.4378x; 2.4378x over previous
#include <cuda_runtime.h>
#include <cuda_bf16.h>
#include <math.h>
#include <stdint.h>

#define Bb 4
#define Tt 128
#define Uu 64
#define Dd 512
#define Hh 640
#define Vv 1024
#define RR (Bb*Tt*Uu)          // 32768 joint rows

// ---------------- scratch (device globals; no allocs allowed) --------------
__device__ float g_ps[Bb*Tt*Hh];
__device__ float g_pt[Bb*Uu*Hh];
__device__ __align__(16) __nv_bfloat16 g_h_hi[(size_t)RR*Hh];   // 40 MB
__device__ __align__(16) __nv_bfloat16 g_h_lo[(size_t)RR*Hh];   // 40 MB
__device__ __align__(16) __nv_bfloat16 g_w_hi[(size_t)Vv*Hh];   // W2^T hi [V][K]
__device__ __align__(16) __nv_bfloat16 g_w_lo[(size_t)Vv*Hh];   // W2^T lo [V][K]

static __device__ __forceinline__ uint32_t s2u(const void* p){
    uint32_t a;
    asm("{ .reg .u64 t; cvta.to.shared.u64 t, %1; cvt.u32.u64 %0, t; }"
        : "=r"(a) : "l"(p));
    return a;
}
#define LDMX4(r0,r1,r2,r3,addr) \
    asm volatile("ldmatrix.sync.aligned.m8n8.x4.shared.b16 {%0,%1,%2,%3}, [%4];" \
        : "=r"(r0),"=r"(r1),"=r"(r2),"=r"(r3) : "r"(addr))
#define MMA16816(d,a,b0,b1) \
    asm volatile("mma.sync.aligned.m16n8k16.row.col.f32.bf16.bf16.f32 " \
        "{%0,%1,%2,%3}, {%4,%5,%6,%7}, {%8,%9}, {%0,%1,%2,%3};" \
        : "+f"((d)[0]),"+f"((d)[1]),"+f"((d)[2]),"+f"((d)[3]) \
        : "r"((a)[0]),"r"((a)[1]),"r"((a)[2]),"r"((a)[3]), "r"(b0),"r"(b1))

// ---------------------------------------------------------------------------
// Kernel 1: proj. 480 CTAs = 96 row-blocks x 5 col-chunks of 128.
// ---------------------------------------------------------------------------
__global__ __launch_bounds__(256) void proj_kernel(
    const float* __restrict__ src, const float* __restrict__ tgt,
    const float* __restrict__ W1, const float* __restrict__ b1) {
    __shared__ float s_in[8 * Dd];
    const int bx = blockIdx.x;
    const int rb = bx / 5, chunk = bx - rb * 5;
    const int row0 = rb * 8;
    const bool is_src = (row0 < Bb * Tt);
    const float* inp = is_src ? src + (size_t)row0 * Dd
                              : tgt + (size_t)(row0 - Bb * Tt) * Dd;
    const float* w = W1 + (is_src ? 0 : (size_t)Dd * Hh);
    float* outp = is_src ? g_ps + (size_t)row0 * Hh
                         : g_pt + (size_t)(row0 - Bb * Tt) * Hh;
    const int tid = threadIdx.x;
    for (int i = tid; i < 8 * Dd; i += 256) s_in[i] = inp[i];
    __syncthreads();

    const int c = chunk * 128 + (tid & 127);
    const int rbase = (tid >> 7) * 4;
    float a0 = 0.f, a1 = 0.f, a2 = 0.f, a3 = 0.f;
#pragma unroll 4
    for (int d = 0; d < Dd; d++) {
        float wv = w[(size_t)d * Hh + c];
        a0 = fmaf(s_in[(rbase + 0) * Dd + d], wv, a0);
        a1 = fmaf(s_in[(rbase + 1) * Dd + d], wv, a1);
        a2 = fmaf(s_in[(rbase + 2) * Dd + d], wv, a2);
        a3 = fmaf(s_in[(rbase + 3) * Dd + d], wv, a3);
    }
    float bb = is_src ? b1[c] : 0.f;
    outp[(size_t)(rbase + 0) * Hh + c] = a0 + bb;
    outp[(size_t)(rbase + 1) * Hh + c] = a1 + bb;
    outp[(size_t)(rbase + 2) * Hh + c] = a2 + bb;
    outp[(size_t)(rbase + 3) * Hh + c] = a3 + bb;
}

// ---------------------------------------------------------------------------
// Kernel 2: W2 split+transpose to bf16 hi/lo, [V][K] K-major.
// Grid must cover Hh*Vv = 655360 elements (fixed from round 9).
// ---------------------------------------------------------------------------
__global__ __launch_bounds__(256) void w2split_kernel(const float* __restrict__ W2) {
    int idx = blockIdx.x * 256 + threadIdx.x;   // = k*Vv + n
    int k = idx >> 10, n = idx & 1023;
    float w = W2[idx];
    __nv_bfloat16 hi = __float2bfloat16(w);
    float lo = w - __bfloat162float(hi);
    g_w_hi[(size_t)n * Hh + k] = hi;
    g_w_lo[(size_t)n * Hh + k] = __float2bfloat16(lo);
}

// ---------------------------------------------------------------------------
// Kernel 3: h = tanh(ps+pt) -> bf16 hi/lo. One warp per row, 8 rows/CTA.
// ---------------------------------------------------------------------------
__global__ __launch_bounds__(256) void h_build_kernel() {
    const int row = blockIdx.x * 8 + (threadIdx.x >> 5);
    const int lane = threadIdx.x & 31;
    const float* psr = g_ps + (size_t)(row >> 6) * Hh;
    const float* ptr = g_pt + (size_t)(((row >> 13) << 6) + (row & 63)) * Hh;
    __nv_bfloat16* hh = g_h_hi + (size_t)row * Hh;
    __nv_bfloat16* hl = g_h_lo + (size_t)row * Hh;
#pragma unroll 5
    for (int j = 0; j < 20; j++) {
        int k = lane + j * 32;
        float x = psr[k] + ptr[k];
        float e; asm("ex2.approx.f32 %0, %1;" : "=f"(e) : "f"(x * 2.8853900817779268f));
        float r; asm("rcp.approx.f32 %0, %1;" : "=f"(r) : "f"(e + 1.0f));
        float v = fmaf(-2.0f, r, 1.0f);
        __nv_bfloat16 hi = __float2bfloat16(v);
        hh[k] = hi;
        hl[k] = __float2bfloat16(v - __bfloat162float(hi));
    }
}

// ---------------------------------------------------------------------------
// Kernel 4: bf16 GEMM via mma.sync.m16n8k16 (HMMA; compiles on compute_103).
// Grid 2048: rb = bx>>3 (128-row block), nb = bx&7 (128-col block).
// 8 warps = 4 row-groups x 2 col-groups; warp tile 32x64.
// K' = 1920 = 30 chunks of 64: segs (h_hi*w_hi, h_lo*w_hi, h_hi*w_lo).
// smem: [A0][B0][A1][B1], each 128 rows x 72 bf16 (pad -> conflict-free).
// ---------------------------------------------------------------------------
#define SROW 72                       // padded row, elements
#define TILE_B (128 * SROW * 2)       // 18432 B
#define GEMM_SMEM (4 * TILE_B)        // 73728 B

__global__ __launch_bounds__(256) void gemm_kernel(float* __restrict__ out) {
    extern __shared__ __align__(16) char smem[];
    const uint32_t sb = s2u(smem);
    const int tid = threadIdx.x;
    const int wid = tid >> 5, lane = tid & 31;
    const int wr = wid & 3, wc = wid >> 2;          // warp row/col group
    const int bx = blockIdx.x, rb = bx >> 3, nb = bx & 7;

    float acc[2][8][4];
#pragma unroll
    for (int mi = 0; mi < 2; mi++)
#pragma unroll
        for (int ni = 0; ni < 8; ni++)
#pragma unroll
            for (int j = 0; j < 4; j++) acc[mi][ni][j] = 0.f;

    // per-thread copy coords: 4 x uint4 each for A and B
    const int cr[4] = { (tid + 0) >> 3, (tid + 256) >> 3, (tid + 512) >> 3, (tid + 768) >> 3 };
    const int cv = (tid & 7) * 16;

    uint4 pre[8];
    auto gload = [&](int c) {
        int seg = (c < 10) ? 0 : ((c < 20) ? 1 : 2);
        int kk = (c - seg * 10) * 64;
        const __nv_bfloat16* As = (seg == 1) ? g_h_lo : g_h_hi;
        const __nv_bfloat16* Bs = (seg == 2) ? g_w_lo : g_w_hi;
        const char* Ab = (const char*)(As + (size_t)rb * 128 * Hh + kk);
        const char* Bp = (const char*)(Bs + (size_t)nb * 128 * Hh + kk);
#pragma unroll
        for (int i = 0; i < 4; i++) {
            pre[i]     = *(const uint4*)(Ab + (size_t)cr[i] * (Hh * 2) + cv);
            pre[4 + i] = *(const uint4*)(Bp + (size_t)cr[i] * (Hh * 2) + cv);
        }
    };
    auto sstore = [&](int buf) {
        char* A = smem + buf * 2 * TILE_B;
        char* B = A + TILE_B;
#pragma unroll
        for (int i = 0; i < 4; i++) {
            *(uint4*)(A + cr[i] * (SROW * 2) + cv) = pre[i];
            *(uint4*)(B + cr[i] * (SROW * 2) + cv) = pre[4 + i];
        }
    };

    // ldmatrix lane-address components (bytes within a buffer)
    const int a_row = wr * 32 + (lane & 15);            // + mi*16
    const int a_kof = ((lane >> 4) << 4);               // 0 or 16 bytes (k+8)
    const int b_row = wc * 64 + ((lane >> 4) << 3) + (lane & 7);  // + p*16
    const int b_kof = (((lane >> 3) & 1) << 4);

    gload(0); sstore(0); __syncthreads();

    for (int c = 0; c < 30; c++) {
        const int buf = c & 1;
        if (c < 29) gload(c + 1);

        const uint32_t sa = sb + buf * 2 * TILE_B;
        const uint32_t sB = sa + TILE_B;
#pragma unroll
        for (int ks = 0; ks < 4; ks++) {
            uint32_t a[2][4];
#pragma unroll
            for (int mi = 0; mi < 2; mi++) {
                uint32_t ad = sa + (a_row + mi * 16) * (SROW * 2) + ks * 32 + a_kof;
                LDMX4(a[mi][0], a[mi][1], a[mi][2], a[mi][3], ad);
            }
            uint32_t bf[4][4];
#pragma unroll
            for (int p = 0; p < 4; p++) {
                uint32_t bd = sB + (b_row + p * 16) * (SROW * 2) + ks * 32 + b_kof;
                LDMX4(bf[p][0], bf[p][1], bf[p][2], bf[p][3], bd);
            }
#pragma unroll
            for (int mi = 0; mi < 2; mi++)
#pragma unroll
                for (int ni = 0; ni < 8; ni++) {
                    uint32_t b0 = bf[ni >> 1][(ni & 1) * 2 + 0];
                    uint32_t b1 = bf[ni >> 1][(ni & 1) * 2 + 1];
                    MMA16816(acc[mi][ni], a[mi], b0, b1);
                }
        }
        if (c < 29) {
            __syncthreads();          // everyone done reading buf^1 (chunk c-1)
            sstore(buf ^ 1);
            __syncthreads();          // buf^1 ready for chunk c+1
        }
    }

    // Epilogue: raw logits. acc row = t/4 (+8 for d2,d3), cols 2*(t%4)(+1).
    const int mb = rb * 128 + wr * 32 + (lane >> 2);
    const int cb = nb * 128 + wc * 64 + 2 * (lane & 3);
#pragma unroll
    for (int mi = 0; mi < 2; mi++)
#pragma unroll
        for (int ni = 0; ni < 8; ni++) {
            int m = mb + mi * 16;
            int cc = cb + ni * 8;
            *(float2*)(out + (size_t)m * Vv + cc) =
                make_float2(acc[mi][ni][0], acc[mi][ni][1]);
            *(float2*)(out + (size_t)(m + 8) * Vv + cc) =
                make_float2(acc[mi][ni][2], acc[mi][ni][3]);
        }
}

// ---------------------------------------------------------------------------
// Kernel 5: in-place out = log_softmax(raw + b2). One warp per row.
// ---------------------------------------------------------------------------
__global__ __launch_bounds__(256) void fixup_kernel(
    float* __restrict__ out, const float* __restrict__ b2) {
    const int row = blockIdx.x * 8 + (threadIdx.x >> 5);
    const int lane = threadIdx.x & 31;
    float4* orow = (float4*)(out + (size_t)row * Vv);
    const float4* b4 = (const float4*)b2;

    float4 v[8];
    float mx = -INFINITY;
#pragma unroll
    for (int j = 0; j < 8; j++) {
        int f = lane + j * 32;
        float4 t = orow[f];
        float4 bbv = b4[f];
        t.x += bbv.x; t.y += bbv.y; t.z += bbv.z; t.w += bbv.w;
        v[j] = t;
        mx = fmaxf(mx, fmaxf(fmaxf(t.x, t.y), fmaxf(t.z, t.w)));
    }
#pragma unroll
    for (int s = 16; s > 0; s >>= 1) mx = fmaxf(mx, __shfl_xor_sync(0xffffffffu, mx, s));
    float sum = 0.f;
#pragma unroll
    for (int j = 0; j < 8; j++)
        sum += __expf(v[j].x - mx) + __expf(v[j].y - mx)
             + __expf(v[j].z - mx) + __expf(v[j].w - mx);
#pragma unroll
    for (int s = 16; s > 0; s >>= 1) sum += __shfl_xor_sync(0xffffffffu, sum, s);
    float lz = mx + __logf(sum);
#pragma unroll
    for (int j = 0; j < 8; j++) {
        float4 t = v[j];
        t.x -= lz; t.y -= lz; t.z -= lz; t.w -= lz;
        orow[lane + j * 32] = t;
    }
}

// ---------------------------------------------------------------------------
__global__ void tail_kernel(const int* __restrict__ sl, const int* __restrict__ tl,
                            float* __restrict__ out, long long base, int tail) {
    int i = threadIdx.x;
    if (i < tail && i < 8) {
        out[base + i] = (i < 4) ? (float)sl[i] : (float)tl[i - 4];
    }
}

extern "C" void kernel_launch(void* const* d_in, const int* in_sizes, int n_in,
                              void* d_out, int out_size) {
    const float* src = (const float*)d_in[0];
    const int*   sl  = (const int*)d_in[1];
    const float* tgt = (const float*)d_in[2];
    const int*   tl  = (const int*)d_in[3];
    const float* W1  = (const float*)d_in[4];
    const float* b1  = (const float*)d_in[5];
    const float* W2  = (const float*)d_in[6];
    const float* b2  = (const float*)d_in[7];
    float* out = (float*)d_out;

    cudaFuncSetAttribute(gemm_kernel,
                         cudaFuncAttributeMaxDynamicSharedMemorySize, GEMM_SMEM);

    proj_kernel<<<480, 256>>>(src, tgt, W1, b1);       // 96 row-blocks x 5
    w2split_kernel<<<(Hh * Vv) / 256, 256>>>(W2);      // 2560 CTAs (full W2!)
    h_build_kernel<<<RR / 8, 256>>>();                 // 4096 CTAs
    gemm_kernel<<<2048, 256, GEMM_SMEM>>>(out);        // 256 rb x 8 nb
    fixup_kernel<<<RR / 8, 256>>>(out, b2);

    long long mainN = (long long)RR * Vv;              // 33554432
    long long tail = (long long)out_size - mainN;
    if (tail > 0) tail_kernel<<<1, 32>>>(sl, tl, out, mainN, (int)tail);
}

// round 12
// speedup vs baseline: 2.4695x; 1.0130x over previous
#include <cuda_runtime.h>
#include <cuda_bf16.h>
#include <math.h>
#include <stdint.h>

#define Bb 4
#define Tt 128
#define Uu 64
#define Dd 512
#define Hh 640
#define Vv 1024
#define RR (Bb*Tt*Uu)          // 32768 joint rows

// ---------------- scratch (device globals; no allocs allowed) --------------
__device__ float g_ps[Bb*Tt*Hh];
__device__ float g_pt[Bb*Uu*Hh];
__device__ __align__(16) __nv_bfloat16 g_h_hi[(size_t)RR*Hh];   // 40 MB
__device__ __align__(16) __nv_bfloat16 g_h_lo[(size_t)RR*Hh];   // 40 MB
__device__ __align__(16) __nv_bfloat16 g_w_hi[(size_t)Vv*Hh];   // W2^T hi [V][K]
__device__ __align__(16) __nv_bfloat16 g_w_lo[(size_t)Vv*Hh];   // W2^T lo [V][K]

static __device__ __forceinline__ uint32_t s2u(const void* p){
    uint32_t a;
    asm("{ .reg .u64 t; cvta.to.shared.u64 t, %1; cvt.u32.u64 %0, t; }"
        : "=r"(a) : "l"(p));
    return a;
}
#define LDMX4(r0,r1,r2,r3,addr) \
    asm volatile("ldmatrix.sync.aligned.m8n8.x4.shared.b16 {%0,%1,%2,%3}, [%4];" \
        : "=r"(r0),"=r"(r1),"=r"(r2),"=r"(r3) : "r"(addr))
#define MMA16816(d,a,b0,b1) \
    asm volatile("mma.sync.aligned.m16n8k16.row.col.f32.bf16.bf16.f32 " \
        "{%0,%1,%2,%3}, {%4,%5,%6,%7}, {%8,%9}, {%0,%1,%2,%3};" \
        : "+f"((d)[0]),"+f"((d)[1]),"+f"((d)[2]),"+f"((d)[3]) \
        : "r"((a)[0]),"r"((a)[1]),"r"((a)[2]),"r"((a)[3]), "r"(b0),"r"(b1))
#define CPA16(dst, src) \
    asm volatile("cp.async.cg.shared.global [%0], [%1], 16;" \
        :: "r"(dst), "l"(__cvta_generic_to_global(src)) : "memory")
#define CP_COMMIT() asm volatile("cp.async.commit_group;" ::: "memory")
#define CP_WAIT(n)  asm volatile("cp.async.wait_group %0;" :: "n"(n) : "memory")

// ---------------------------------------------------------------------------
// Kernel 1: proj. 480 CTAs = 96 row-blocks x 5 col-chunks of 128.
// ---------------------------------------------------------------------------
__global__ __launch_bounds__(256) void proj_kernel(
    const float* __restrict__ src, const float* __restrict__ tgt,
    const float* __restrict__ W1, const float* __restrict__ b1) {
    __shared__ float s_in[8 * Dd];
    const int bx = blockIdx.x;
    const int rb = bx / 5, chunk = bx - rb * 5;
    const int row0 = rb * 8;
    const bool is_src = (row0 < Bb * Tt);
    const float* inp = is_src ? src + (size_t)row0 * Dd
                              : tgt + (size_t)(row0 - Bb * Tt) * Dd;
    const float* w = W1 + (is_src ? 0 : (size_t)Dd * Hh);
    float* outp = is_src ? g_ps + (size_t)row0 * Hh
                         : g_pt + (size_t)(row0 - Bb * Tt) * Hh;
    const int tid = threadIdx.x;
    for (int i = tid; i < 8 * Dd; i += 256) s_in[i] = inp[i];
    __syncthreads();

    const int c = chunk * 128 + (tid & 127);
    const int rbase = (tid >> 7) * 4;
    float a0 = 0.f, a1 = 0.f, a2 = 0.f, a3 = 0.f;
#pragma unroll 4
    for (int d = 0; d < Dd; d++) {
        float wv = w[(size_t)d * Hh + c];
        a0 = fmaf(s_in[(rbase + 0) * Dd + d], wv, a0);
        a1 = fmaf(s_in[(rbase + 1) * Dd + d], wv, a1);
        a2 = fmaf(s_in[(rbase + 2) * Dd + d], wv, a2);
        a3 = fmaf(s_in[(rbase + 3) * Dd + d], wv, a3);
    }
    float bb = is_src ? b1[c] : 0.f;
    outp[(size_t)(rbase + 0) * Hh + c] = a0 + bb;
    outp[(size_t)(rbase + 1) * Hh + c] = a1 + bb;
    outp[(size_t)(rbase + 2) * Hh + c] = a2 + bb;
    outp[(size_t)(rbase + 3) * Hh + c] = a3 + bb;
}

// ---------------------------------------------------------------------------
// Kernel 2: W2 split+transpose to bf16 hi/lo, [V][K] K-major.
// ---------------------------------------------------------------------------
__global__ __launch_bounds__(256) void w2split_kernel(const float* __restrict__ W2) {
    int idx = blockIdx.x * 256 + threadIdx.x;   // = k*Vv + n
    int k = idx >> 10, n = idx & 1023;
    float w = W2[idx];
    __nv_bfloat16 hi = __float2bfloat16(w);
    float lo = w - __bfloat162float(hi);
    g_w_hi[(size_t)n * Hh + k] = hi;
    g_w_lo[(size_t)n * Hh + k] = __float2bfloat16(lo);
}

// ---------------------------------------------------------------------------
// Kernel 3: h = tanh(ps+pt) -> bf16 hi/lo. One warp per row, 8 rows/CTA.
// ---------------------------------------------------------------------------
__global__ __launch_bounds__(256) void h_build_kernel() {
    const int row = blockIdx.x * 8 + (threadIdx.x >> 5);
    const int lane = threadIdx.x & 31;
    const float* psr = g_ps + (size_t)(row >> 6) * Hh;
    const float* ptr = g_pt + (size_t)(((row >> 13) << 6) + (row & 63)) * Hh;
    __nv_bfloat16* hh = g_h_hi + (size_t)row * Hh;
    __nv_bfloat16* hl = g_h_lo + (size_t)row * Hh;
#pragma unroll 5
    for (int j = 0; j < 20; j++) {
        int k = lane + j * 32;
        float x = psr[k] + ptr[k];
        float e; asm("ex2.approx.f32 %0, %1;" : "=f"(e) : "f"(x * 2.8853900817779268f));
        float r; asm("rcp.approx.f32 %0, %1;" : "=f"(r) : "f"(e + 1.0f));
        float v = fmaf(-2.0f, r, 1.0f);
        __nv_bfloat16 hi = __float2bfloat16(v);
        hh[k] = hi;
        hl[k] = __float2bfloat16(v - __bfloat162float(hi));
    }
}

// ---------------------------------------------------------------------------
// Kernel 4: bf16 GEMM, mma.sync m16n8k16. CTA tile 128 rows x 256 cols.
// Grid 1024: rb = bx>>2 (128-row block), nb = bx&3 (256-col block).
// 8 warps = 2 row-groups x 4 col-groups; warp tile 64x64 (32 MMAs / 8 ldmx4).
// K' = 1920 = 30 chunks of 64: segs (h_hi*w_hi, h_lo*w_hi, h_hi*w_lo).
// cp.async.cg double-buffered staging (2 groups in flight).
// smem rows padded to 72 elems (144 B) -> conflict-free ldmatrix.
// ---------------------------------------------------------------------------
#define SROW 72
#define A_TILE (128 * SROW * 2)            // 18432 B
#define B_TILE (256 * SROW * 2)            // 36864 B
#define BUF_B  (A_TILE + B_TILE)           // 55296 B
#define GEMM_SMEM (2 * BUF_B)              // 110592 B

__global__ __launch_bounds__(256) void gemm_kernel(float* __restrict__ out) {
    extern __shared__ __align__(16) char smem[];
    const uint32_t sb = s2u(smem);
    const int tid = threadIdx.x;
    const int wid = tid >> 5, lane = tid & 31;
    const int wr = wid & 1, wc = wid >> 1;           // 2 x 4 warp grid
    const int bx = blockIdx.x, rb = bx >> 2, nb = bx & 3;

    float acc[4][8][4];
#pragma unroll
    for (int mi = 0; mi < 4; mi++)
#pragma unroll
        for (int ni = 0; ni < 8; ni++)
#pragma unroll
            for (int j = 0; j < 4; j++) acc[mi][ni][j] = 0.f;

    // cp.async staging: A 1024 16B-ops, B 2048 16B-ops, 12 per thread
    auto issue = [&](int c, int buf) {
        int seg = (c < 10) ? 0 : ((c < 20) ? 1 : 2);
        int kk = (c - seg * 10) * 64;
        const __nv_bfloat16* As = (seg == 1) ? g_h_lo : g_h_hi;
        const __nv_bfloat16* Bs = (seg == 2) ? g_w_lo : g_w_hi;
        const char* Ab = (const char*)(As + (size_t)rb * 128 * Hh + kk);
        const char* Bp = (const char*)(Bs + (size_t)nb * 256 * Hh + kk);
        const uint32_t sA = sb + buf * BUF_B;
        const uint32_t sB = sA + A_TILE;
#pragma unroll
        for (int t = 0; t < 4; t++) {
            int i = tid + t * 256, r = i >> 3, v = i & 7;
            CPA16(sA + r * (SROW * 2) + v * 16, Ab + (size_t)r * (Hh * 2) + v * 16);
        }
#pragma unroll
        for (int t = 0; t < 8; t++) {
            int i = tid + t * 256, n = i >> 3, v = i & 7;
            CPA16(sB + n * (SROW * 2) + v * 16, Bp + (size_t)n * (Hh * 2) + v * 16);
        }
    };

    // ldmatrix lane-address components (hardware-verified in round 10)
    const int a_row = wr * 64 + (lane & 15);                       // + mi*16
    const int a_kof = ((lane >> 4) << 4);
    const int b_row = wc * 64 + ((lane >> 4) << 3) + (lane & 7);   // + p*16
    const int b_kof = (((lane >> 3) & 1) << 4);

    issue(0, 0); CP_COMMIT();
    issue(1, 1); CP_COMMIT();

    for (int c = 0; c < 30; c++) {
        const int buf = c & 1;
        if (c < 28) { CP_WAIT(1); } else { CP_WAIT(0); }
        __syncthreads();

        const uint32_t sA = sb + buf * BUF_B;
        const uint32_t sB = sA + A_TILE;
#pragma unroll
        for (int ks = 0; ks < 4; ks++) {
            uint32_t a[4][4];
#pragma unroll
            for (int mi = 0; mi < 4; mi++) {
                uint32_t ad = sA + (a_row + mi * 16) * (SROW * 2) + ks * 32 + a_kof;
                LDMX4(a[mi][0], a[mi][1], a[mi][2], a[mi][3], ad);
            }
            uint32_t bf[4][4];
#pragma unroll
            for (int p = 0; p < 4; p++) {
                uint32_t bd = sB + (b_row + p * 16) * (SROW * 2) + ks * 32 + b_kof;
                LDMX4(bf[p][0], bf[p][1], bf[p][2], bf[p][3], bd);
            }
#pragma unroll
            for (int mi = 0; mi < 4; mi++)
#pragma unroll
                for (int ni = 0; ni < 8; ni++) {
                    uint32_t b0 = bf[ni >> 1][(ni & 1) * 2 + 0];
                    uint32_t b1 = bf[ni >> 1][(ni & 1) * 2 + 1];
                    MMA16816(acc[mi][ni], a[mi], b0, b1);
                }
        }
        if (c + 2 < 30) {
            __syncthreads();            // all warps done reading buf
            issue(c + 2, buf); CP_COMMIT();
        }
    }

    // Epilogue: raw logits (verified mapping; rows +8 for acc[2],[3])
    const int mb = rb * 128 + wr * 64 + (lane >> 2);
    const int cb = nb * 256 + wc * 64 + 2 * (lane & 3);
#pragma unroll
    for (int mi = 0; mi < 4; mi++)
#pragma unroll
        for (int ni = 0; ni < 8; ni++) {
            int m = mb + mi * 16;
            int cc = cb + ni * 8;
            *(float2*)(out + (size_t)m * Vv + cc) =
                make_float2(acc[mi][ni][0], acc[mi][ni][1]);
            *(float2*)(out + (size_t)(m + 8) * Vv + cc) =
                make_float2(acc[mi][ni][2], acc[mi][ni][3]);
        }
}

// ---------------------------------------------------------------------------
// Kernel 5: in-place out = log_softmax(raw + b2). One warp per row.
// ---------------------------------------------------------------------------
__global__ __launch_bounds__(256) void fixup_kernel(
    float* __restrict__ out, const float* __restrict__ b2) {
    const int row = blockIdx.x * 8 + (threadIdx.x >> 5);
    const int lane = threadIdx.x & 31;
    float4* orow = (float4*)(out + (size_t)row * Vv);
    const float4* b4 = (const float4*)b2;

    float4 v[8];
    float mx = -INFINITY;
#pragma unroll
    for (int j = 0; j < 8; j++) {
        int f = lane + j * 32;
        float4 t = orow[f];
        float4 bbv = b4[f];
        t.x += bbv.x; t.y += bbv.y; t.z += bbv.z; t.w += bbv.w;
        v[j] = t;
        mx = fmaxf(mx, fmaxf(fmaxf(t.x, t.y), fmaxf(t.z, t.w)));
    }
#pragma unroll
    for (int s = 16; s > 0; s >>= 1) mx = fmaxf(mx, __shfl_xor_sync(0xffffffffu, mx, s));
    float sum = 0.f;
#pragma unroll
    for (int j = 0; j < 8; j++)
        sum += __expf(v[j].x - mx) + __expf(v[j].y - mx)
             + __expf(v[j].z - mx) + __expf(v[j].w - mx);
#pragma unroll
    for (int s = 16; s > 0; s >>= 1) sum += __shfl_xor_sync(0xffffffffu, sum, s);
    float lz = mx + __logf(sum);
#pragma unroll
    for (int j = 0; j < 8; j++) {
        float4 t = v[j];
        t.x -= lz; t.y -= lz; t.z -= lz; t.w -= lz;
        orow[lane + j * 32] = t;
    }
}

// ---------------------------------------------------------------------------
__global__ void tail_kernel(const int* __restrict__ sl, const int* __restrict__ tl,
                            float* __restrict__ out, long long base, int tail) {
    int i = threadIdx.x;
    if (i < tail && i < 8) {
        out[base + i] = (i < 4) ? (float)sl[i] : (float)tl[i - 4];
    }
}

extern "C" void kernel_launch(void* const* d_in, const int* in_sizes, int n_in,
                              void* d_out, int out_size) {
    const float* src = (const float*)d_in[0];
    const int*   sl  = (const int*)d_in[1];
    const float* tgt = (const float*)d_in[2];
    const int*   tl  = (const int*)d_in[3];
    const float* W1  = (const float*)d_in[4];
    const float* b1  = (const float*)d_in[5];
    const float* W2  = (const float*)d_in[6];
    const float* b2  = (const float*)d_in[7];
    float* out = (float*)d_out;

    cudaFuncSetAttribute(gemm_kernel,
                         cudaFuncAttributeMaxDynamicSharedMemorySize, GEMM_SMEM);

    proj_kernel<<<480, 256>>>(src, tgt, W1, b1);       // 96 row-blocks x 5
    w2split_kernel<<<(Hh * Vv) / 256, 256>>>(W2);      // 2560 CTAs
    h_build_kernel<<<RR / 8, 256>>>();                 // 4096 CTAs
    gemm_kernel<<<1024, 256, GEMM_SMEM>>>(out);        // 256 rb x 4 nb
    fixup_kernel<<<RR / 8, 256>>>(out, b2);

    long long mainN = (long long)RR * Vv;              // 33554432
    long long tail = (long long)out_size - mainN;
    if (tail > 0) tail_kernel<<<1, 32>>>(sl, tl, out, mainN, (int)tail);
}

// round 14
// speedup vs baseline: 3.5095x; 1.4211x over previous
#include <cuda_runtime.h>
#include <cuda_bf16.h>
#include <math.h>
#include <stdint.h>

#define Bb 4
#define Tt 128
#define Uu 64
#define Dd 512
#define Hh 640
#define Vv 1024
#define RR (Bb*Tt*Uu)          // 32768 joint rows

// ---------------- scratch (device globals; no allocs allowed) --------------
__device__ float g_ps[Bb*Tt*Hh];
__device__ float g_pt[Bb*Uu*Hh];
__device__ __align__(16) __nv_bfloat16 g_h_hi[(size_t)RR*Hh];   // 40 MB
__device__ __align__(16) __nv_bfloat16 g_h_lo[(size_t)RR*Hh];   // 40 MB
__device__ __align__(16) __nv_bfloat16 g_w_hi[(size_t)Vv*Hh];   // W2^T hi [V][K]

static __device__ __forceinline__ uint32_t s2u(const void* p){
    uint32_t a;
    asm("{ .reg .u64 t; cvta.to.shared.u64 t, %1; cvt.u32.u64 %0, t; }"
        : "=r"(a) : "l"(p));
    return a;
}
#define LDMX4(r0,r1,r2,r3,addr) \
    asm volatile("ldmatrix.sync.aligned.m8n8.x4.shared.b16 {%0,%1,%2,%3}, [%4];" \
        : "=r"(r0),"=r"(r1),"=r"(r2),"=r"(r3) : "r"(addr))
#define MMA16816(d,a,b0,b1) \
    asm volatile("mma.sync.aligned.m16n8k16.row.col.f32.bf16.bf16.f32 " \
        "{%0,%1,%2,%3}, {%4,%5,%6,%7}, {%8,%9}, {%0,%1,%2,%3};" \
        : "+f"((d)[0]),"+f"((d)[1]),"+f"((d)[2]),"+f"((d)[3]) \
        : "r"((a)[0]),"r"((a)[1]),"r"((a)[2]),"r"((a)[3]), "r"(b0),"r"(b1))
#define CPA16(dst, src) \
    asm volatile("cp.async.cg.shared.global [%0], [%1], 16;" \
        :: "r"(dst), "l"(__cvta_generic_to_global(src)) : "memory")
#define CP_COMMIT() asm volatile("cp.async.commit_group;" ::: "memory")
#define CP_WAIT(n)  asm volatile("cp.async.wait_group %0;" :: "n"(n) : "memory")

// ---------------------------------------------------------------------------
// Kernel 1: proj. 480 CTAs = 96 row-blocks x 5 col-chunks of 128.
// ---------------------------------------------------------------------------
__global__ __launch_bounds__(256) void proj_kernel(
    const float* __restrict__ src, const float* __restrict__ tgt,
    const float* __restrict__ W1, const float* __restrict__ b1) {
    __shared__ float s_in[8 * Dd];
    const int bx = blockIdx.x;
    const int rb = bx / 5, chunk = bx - rb * 5;
    const int row0 = rb * 8;
    const bool is_src = (row0 < Bb * Tt);
    const float* inp = is_src ? src + (size_t)row0 * Dd
                              : tgt + (size_t)(row0 - Bb * Tt) * Dd;
    const float* w = W1 + (is_src ? 0 : (size_t)Dd * Hh);
    float* outp = is_src ? g_ps + (size_t)row0 * Hh
                         : g_pt + (size_t)(row0 - Bb * Tt) * Hh;
    const int tid = threadIdx.x;
    for (int i = tid; i < 8 * Dd; i += 256) s_in[i] = inp[i];
    __syncthreads();

    const int c = chunk * 128 + (tid & 127);
    const int rbase = (tid >> 7) * 4;
    float a0 = 0.f, a1 = 0.f, a2 = 0.f, a3 = 0.f;
#pragma unroll 4
    for (int d = 0; d < Dd; d++) {
        float wv = w[(size_t)d * Hh + c];
        a0 = fmaf(s_in[(rbase + 0) * Dd + d], wv, a0);
        a1 = fmaf(s_in[(rbase + 1) * Dd + d], wv, a1);
        a2 = fmaf(s_in[(rbase + 2) * Dd + d], wv, a2);
        a3 = fmaf(s_in[(rbase + 3) * Dd + d], wv, a3);
    }
    float bb = is_src ? b1[c] : 0.f;
    outp[(size_t)(rbase + 0) * Hh + c] = a0 + bb;
    outp[(size_t)(rbase + 1) * Hh + c] = a1 + bb;
    outp[(size_t)(rbase + 2) * Hh + c] = a2 + bb;
    outp[(size_t)(rbase + 3) * Hh + c] = a3 + bb;
}

// ---------------------------------------------------------------------------
// Kernel 2: W2 -> bf16 hi transpose, [V][K] K-major. (lo term dropped: the
// h*w_lo contribution is ~1e-4 norm-rel, 10x under threshold.)
// ---------------------------------------------------------------------------
__global__ __launch_bounds__(256) void w2split_kernel(const float* __restrict__ W2) {
    int idx = blockIdx.x * 256 + threadIdx.x;   // = k*Vv + n
    int k = idx >> 10, n = idx & 1023;
    g_w_hi[(size_t)n * Hh + k] = __float2bfloat16(W2[idx]);
}

// ---------------------------------------------------------------------------
// Kernel 3: h = tanh(ps+pt) -> bf16 hi/lo. One warp per row, 8 rows/CTA.
// ---------------------------------------------------------------------------
__global__ __launch_bounds__(256) void h_build_kernel() {
    const int row = blockIdx.x * 8 + (threadIdx.x >> 5);
    const int lane = threadIdx.x & 31;
    const float* psr = g_ps + (size_t)(row >> 6) * Hh;
    const float* ptr = g_pt + (size_t)(((row >> 13) << 6) + (row & 63)) * Hh;
    __nv_bfloat16* hh = g_h_hi + (size_t)row * Hh;
    __nv_bfloat16* hl = g_h_lo + (size_t)row * Hh;
#pragma unroll 5
    for (int j = 0; j < 20; j++) {
        int k = lane + j * 32;
        float x = psr[k] + ptr[k];
        float e; asm("ex2.approx.f32 %0, %1;" : "=f"(e) : "f"(x * 2.8853900817779268f));
        float r; asm("rcp.approx.f32 %0, %1;" : "=f"(r) : "f"(e + 1.0f));
        float v = fmaf(-2.0f, r, 1.0f);
        __nv_bfloat16 hi = __float2bfloat16(v);
        hh[k] = hi;
        hl[k] = __float2bfloat16(v - __bfloat162float(hi));
    }
}

// ---------------------------------------------------------------------------
// Kernel 4: bf16 GEMM, mma.sync m16n8k16. CTA tile 128 rows x 256 cols.
// logits = (h_hi + h_lo) @ w_hi : both A segments share ONE B tile (w_hi),
// so B is loaded & ldmatrix'd once and consumed by 2x MMAs.
// 10 K-chunks of 64. Buffer = {A_hi, A_lo, B}; cp.async double-buffered.
// 8 warps = 2 row-groups x 4 col-groups; warp tile 64x64.
// smem rows padded to 72 elems -> conflict-free ldmatrix.
// ---------------------------------------------------------------------------
#define SROW 72
#define A_TILE (128 * SROW * 2)            // 18432 B
#define B_TILE (256 * SROW * 2)            // 36864 B
#define BUF_B  (2 * A_TILE + B_TILE)       // 73728 B
#define GEMM_SMEM (2 * BUF_B)              // 147456 B

__global__ __launch_bounds__(256) void gemm_kernel(float* __restrict__ out) {
    extern __shared__ __align__(16) char smem[];
    const uint32_t sb = s2u(smem);
    const int tid = threadIdx.x;
    const int wid = tid >> 5, lane = tid & 31;
    const int wr = wid & 1, wc = wid >> 1;           // 2 x 4 warp grid
    const int bx = blockIdx.x, rb = bx >> 2, nb = bx & 3;

    float acc[4][8][4];
#pragma unroll
    for (int mi = 0; mi < 4; mi++)
#pragma unroll
        for (int ni = 0; ni < 8; ni++)
#pragma unroll
            for (int j = 0; j < 4; j++) acc[mi][ni][j] = 0.f;

    // cp.async staging: A_hi 1024 + A_lo 1024 + B 2048 16B-ops = 16/thread
    auto issue = [&](int c, int buf) {
        int kk = c * 64;
        const char* Ah = (const char*)(g_h_hi + (size_t)rb * 128 * Hh + kk);
        const char* Al = (const char*)(g_h_lo + (size_t)rb * 128 * Hh + kk);
        const char* Bp = (const char*)(g_w_hi + (size_t)nb * 256 * Hh + kk);
        const uint32_t sAh = sb + buf * BUF_B;
        const uint32_t sAl = sAh + A_TILE;
        const uint32_t sB  = sAh + 2 * A_TILE;
#pragma unroll
        for (int t = 0; t < 4; t++) {
            int i = tid + t * 256, r = i >> 3, v = i & 7;
            CPA16(sAh + r * (SROW * 2) + v * 16, Ah + (size_t)r * (Hh * 2) + v * 16);
        }
#pragma unroll
        for (int t = 0; t < 4; t++) {
            int i = tid + t * 256, r = i >> 3, v = i & 7;
            CPA16(sAl + r * (SROW * 2) + v * 16, Al + (size_t)r * (Hh * 2) + v * 16);
        }
#pragma unroll
        for (int t = 0; t < 8; t++) {
            int i = tid + t * 256, n = i >> 3, v = i & 7;
            CPA16(sB + n * (SROW * 2) + v * 16, Bp + (size_t)n * (Hh * 2) + v * 16);
        }
    };

    // ldmatrix lane-address components (hardware-verified in rounds 10/11)
    const int a_row = wr * 64 + (lane & 15);                       // + mi*16
    const int a_kof = ((lane >> 4) << 4);
    const int b_row = wc * 64 + ((lane >> 4) << 3) + (lane & 7);   // + p*16
    const int b_kof = (((lane >> 3) & 1) << 4);

    issue(0, 0); CP_COMMIT();
    issue(1, 1); CP_COMMIT();

    for (int c = 0; c < 10; c++) {
        const int buf = c & 1;
        if (c < 8) { CP_WAIT(1); } else { CP_WAIT(0); }
        __syncthreads();

        const uint32_t sAh = sb + buf * BUF_B;
        const uint32_t sAl = sAh + A_TILE;
        const uint32_t sB  = sAh + 2 * A_TILE;
#pragma unroll
        for (int ks = 0; ks < 4; ks++) {
            uint32_t bf[4][4];
#pragma unroll
            for (int p = 0; p < 4; p++) {
                uint32_t bd = sB + (b_row + p * 16) * (SROW * 2) + ks * 32 + b_kof;
                LDMX4(bf[p][0], bf[p][1], bf[p][2], bf[p][3], bd);
            }
            uint32_t ah[4][4], al[4][4];
#pragma unroll
            for (int mi = 0; mi < 4; mi++) {
                uint32_t r0 = (a_row + mi * 16) * (SROW * 2) + ks * 32 + a_kof;
                LDMX4(ah[mi][0], ah[mi][1], ah[mi][2], ah[mi][3], sAh + r0);
                LDMX4(al[mi][0], al[mi][1], al[mi][2], al[mi][3], sAl + r0);
            }
#pragma unroll
            for (int mi = 0; mi < 4; mi++)
#pragma unroll
                for (int ni = 0; ni < 8; ni++) {
                    uint32_t b0 = bf[ni >> 1][(ni & 1) * 2 + 0];
                    uint32_t b1 = bf[ni >> 1][(ni & 1) * 2 + 1];
                    MMA16816(acc[mi][ni], ah[mi], b0, b1);
                    MMA16816(acc[mi][ni], al[mi], b0, b1);
                }
        }
        if (c + 2 < 10) {
            __syncthreads();            // all warps done reading buf
            issue(c + 2, buf); CP_COMMIT();
        }
    }

    // Epilogue: raw logits (verified mapping; rows +8 for d2,d3)
    const int mb = rb * 128 + wr * 64 + (lane >> 2);
    const int cb = nb * 256 + wc * 64 + 2 * (lane & 3);
#pragma unroll
    for (int mi = 0; mi < 4; mi++)
#pragma unroll
        for (int ni = 0; ni < 8; ni++) {
            int m = mb + mi * 16;
            int cc = cb + ni * 8;
            *(float2*)(out + (size_t)m * Vv + cc) =
                make_float2(acc[mi][ni][0], acc[mi][ni][1]);
            *(float2*)(out + (size_t)(m + 8) * Vv + cc) =
                make_float2(acc[mi][ni][2], acc[mi][ni][3]);
        }
}

// ---------------------------------------------------------------------------
// Kernel 5: in-place out = log_softmax(raw + b2). One warp per row.
// ---------------------------------------------------------------------------
__global__ __launch_bounds__(256) void fixup_kernel(
    float* __restrict__ out, const float* __restrict__ b2) {
    const int row = blockIdx.x * 8 + (threadIdx.x >> 5);
    const int lane = threadIdx.x & 31;
    float4* orow = (float4*)(out + (size_t)row * Vv);
    const float4* b4 = (const float4*)b2;

    float4 v[8];
    float mx = -INFINITY;
#pragma unroll
    for (int j = 0; j < 8; j++) {
        int f = lane + j * 32;
        float4 t = orow[f];
        float4 bbv = b4[f];
        t.x += bbv.x; t.y += bbv.y; t.z += bbv.z; t.w += bbv.w;
        v[j] = t;
        mx = fmaxf(mx, fmaxf(fmaxf(t.x, t.y), fmaxf(t.z, t.w)));
    }
#pragma unroll
    for (int s = 16; s > 0; s >>= 1) mx = fmaxf(mx, __shfl_xor_sync(0xffffffffu, mx, s));
    float sum = 0.f;
#pragma unroll
    for (int j = 0; j < 8; j++)
        sum += __expf(v[j].x - mx) + __expf(v[j].y - mx)
             + __expf(v[j].z - mx) + __expf(v[j].w - mx);
#pragma unroll
    for (int s = 16; s > 0; s >>= 1) sum += __shfl_xor_sync(0xffffffffu, sum, s);
    float lz = mx + __logf(sum);
#pragma unroll
    for (int j = 0; j < 8; j++) {
        float4 t = v[j];
        t.x -= lz; t.y -= lz; t.z -= lz; t.w -= lz;
        orow[lane + j * 32] = t;
    }
}

// ---------------------------------------------------------------------------
__global__ void tail_kernel(const int* __restrict__ sl, const int* __restrict__ tl,
                            float* __restrict__ out, long long base, int tail) {
    int i = threadIdx.x;
    if (i < tail && i < 8) {
        out[base + i] = (i < 4) ? (float)sl[i] : (float)tl[i - 4];
    }
}

extern "C" void kernel_launch(void* const* d_in, const int* in_sizes, int n_in,
                              void* d_out, int out_size) {
    const float* src = (const float*)d_in[0];
    const int*   sl  = (const int*)d_in[1];
    const float* tgt = (const float*)d_in[2];
    const int*   tl  = (const int*)d_in[3];
    const float* W1  = (const float*)d_in[4];
    const float* b1  = (const float*)d_in[5];
    const float* W2  = (const float*)d_in[6];
    const float* b2  = (const float*)d_in[7];
    float* out = (float*)d_out;

    cudaFuncSetAttribute(gemm_kernel,
                         cudaFuncAttributeMaxDynamicSharedMemorySize, GEMM_SMEM);

    proj_kernel<<<480, 256>>>(src, tgt, W1, b1);       // 96 row-blocks x 5
    w2split_kernel<<<(Hh * Vv) / 256, 256>>>(W2);      // 2560 CTAs
    h_build_kernel<<<RR / 8, 256>>>();                 // 4096 CTAs
    gemm_kernel<<<1024, 256, GEMM_SMEM>>>(out);        // 256 rb x 4 nb
    fixup_kernel<<<RR / 8, 256>>>(out, b2);

    long long mainN = (long long)RR * Vv;              // 33554432
    long long tail = (long long)out_size - mainN;
    if (tail > 0) tail_kernel<<<1, 32>>>(sl, tl, out, mainN, (int)tail);
}

// round 16
// speedup vs baseline: 4.5968x; 1.3098x over previous
#include <cuda_runtime.h>
#include <cuda_bf16.h>
#include <math.h>
#include <stdint.h>

#define Bb 4
#define Tt 128
#define Uu 64
#define Dd 512
#define Hh 640
#define Vv 1024
#define RR (Bb*Tt*Uu)          // 32768 joint rows

// ---------------- scratch (device globals; no allocs allowed) --------------
__device__ float g_ps[Bb*Tt*Hh];
__device__ float g_pt[Bb*Uu*Hh];
__device__ __align__(16) __nv_bfloat16 g_h_hi[(size_t)RR*Hh];   // 40 MB
__device__ __align__(16) __nv_bfloat16 g_w_hi[(size_t)Vv*Hh];   // W2^T bf16 [V][K]

static __device__ __forceinline__ uint32_t s2u(const void* p){
    uint32_t a;
    asm("{ .reg .u64 t; cvta.to.shared.u64 t, %1; cvt.u32.u64 %0, t; }"
        : "=r"(a) : "l"(p));
    return a;
}
#define LDMX4(r0,r1,r2,r3,addr) \
    asm volatile("ldmatrix.sync.aligned.m8n8.x4.shared.b16 {%0,%1,%2,%3}, [%4];" \
        : "=r"(r0),"=r"(r1),"=r"(r2),"=r"(r3) : "r"(addr))
#define MMA16816(d,a,b0,b1) \
    asm volatile("mma.sync.aligned.m16n8k16.row.col.f32.bf16.bf16.f32 " \
        "{%0,%1,%2,%3}, {%4,%5,%6,%7}, {%8,%9}, {%0,%1,%2,%3};" \
        : "+f"((d)[0]),"+f"((d)[1]),"+f"((d)[2]),"+f"((d)[3]) \
        : "r"((a)[0]),"r"((a)[1]),"r"((a)[2]),"r"((a)[3]), "r"(b0),"r"(b1))
#define CPA16(dst, src) \
    asm volatile("cp.async.cg.shared.global [%0], [%1], 16;" \
        :: "r"(dst), "l"(__cvta_generic_to_global(src)) : "memory")
#define CP_COMMIT() asm volatile("cp.async.commit_group;" ::: "memory")
#define CP_WAIT(n)  asm volatile("cp.async.wait_group %0;" :: "n"(n) : "memory")

// ---------------------------------------------------------------------------
// Kernel 1: proj. 480 CTAs = 96 row-blocks x 5 col-chunks of 128.
// ---------------------------------------------------------------------------
__global__ __launch_bounds__(256) void proj_kernel(
    const float* __restrict__ src, const float* __restrict__ tgt,
    const float* __restrict__ W1, const float* __restrict__ b1) {
    __shared__ float s_in[8 * Dd];
    const int bx = blockIdx.x;
    const int rb = bx / 5, chunk = bx - rb * 5;
    const int row0 = rb * 8;
    const bool is_src = (row0 < Bb * Tt);
    const float* inp = is_src ? src + (size_t)row0 * Dd
                              : tgt + (size_t)(row0 - Bb * Tt) * Dd;
    const float* w = W1 + (is_src ? 0 : (size_t)Dd * Hh);
    float* outp = is_src ? g_ps + (size_t)row0 * Hh
                         : g_pt + (size_t)(row0 - Bb * Tt) * Hh;
    const int tid = threadIdx.x;
    for (int i = tid; i < 8 * Dd; i += 256) s_in[i] = inp[i];
    __syncthreads();

    const int c = chunk * 128 + (tid & 127);
    const int rbase = (tid >> 7) * 4;
    float a0 = 0.f, a1 = 0.f, a2 = 0.f, a3 = 0.f;
#pragma unroll 4
    for (int d = 0; d < Dd; d++) {
        float wv = w[(size_t)d * Hh + c];
        a0 = fmaf(s_in[(rbase + 0) * Dd + d], wv, a0);
        a1 = fmaf(s_in[(rbase + 1) * Dd + d], wv, a1);
        a2 = fmaf(s_in[(rbase + 2) * Dd + d], wv, a2);
        a3 = fmaf(s_in[(rbase + 3) * Dd + d], wv, a3);
    }
    float bb = is_src ? b1[c] : 0.f;
    outp[(size_t)(rbase + 0) * Hh + c] = a0 + bb;
    outp[(size_t)(rbase + 1) * Hh + c] = a1 + bb;
    outp[(size_t)(rbase + 2) * Hh + c] = a2 + bb;
    outp[(size_t)(rbase + 3) * Hh + c] = a3 + bb;
}

// ---------------------------------------------------------------------------
// Kernel 2: W2 -> bf16 transpose, [V][K] K-major.
// ---------------------------------------------------------------------------
__global__ __launch_bounds__(256) void w2split_kernel(const float* __restrict__ W2) {
    int idx = blockIdx.x * 256 + threadIdx.x;   // = k*Vv + n
    int k = idx >> 10, n = idx & 1023;
    g_w_hi[(size_t)n * Hh + k] = __float2bfloat16(W2[idx]);
}

// ---------------------------------------------------------------------------
// Kernel 3: h = tanh(ps+pt) -> bf16. One warp per row, 8 rows/CTA.
// (single bf16 copy; calibrated error model says the lo-residual GEMM terms
//  contribute ~1e-4 norm-rel each; combined stays 3-5x under 1e-3.)
// ---------------------------------------------------------------------------
__global__ __launch_bounds__(256) void h_build_kernel() {
    const int row = blockIdx.x * 8 + (threadIdx.x >> 5);
    const int lane = threadIdx.x & 31;
    const float* psr = g_ps + (size_t)(row >> 6) * Hh;
    const float* ptr = g_pt + (size_t)(((row >> 13) << 6) + (row & 63)) * Hh;
    __nv_bfloat16* hh = g_h_hi + (size_t)row * Hh;
#pragma unroll 5
    for (int j = 0; j < 20; j++) {
        int k = lane + j * 32;
        float x = psr[k] + ptr[k];
        float e; asm("ex2.approx.f32 %0, %1;" : "=f"(e) : "f"(x * 2.8853900817779268f));
        float r; asm("rcp.approx.f32 %0, %1;" : "=f"(r) : "f"(e + 1.0f));
        hh[k] = __float2bfloat16(fmaf(-2.0f, r, 1.0f));
    }
}

// ---------------------------------------------------------------------------
// Kernel 4: single bf16 GEMM, mma.sync m16n8k16. K = 640 (10 chunks of 64).
// CTA tile 128 rows x 256 cols; grid 1024 (rb = bx>>2, nb = bx&3).
// 8 warps = 2 row-groups x 4 col-groups; warp tile 64x64.
// cp.async.cg double-buffered; smem rows padded to 72 elems.
// ---------------------------------------------------------------------------
#define SROW 72
#define A_TILE (128 * SROW * 2)            // 18432 B
#define B_TILE (256 * SROW * 2)            // 36864 B
#define BUF_B  (A_TILE + B_TILE)           // 55296 B
#define GEMM_SMEM (2 * BUF_B)              // 110592 B

__global__ __launch_bounds__(256) void gemm_kernel(float* __restrict__ out) {
    extern __shared__ __align__(16) char smem[];
    const uint32_t sb = s2u(smem);
    const int tid = threadIdx.x;
    const int wid = tid >> 5, lane = tid & 31;
    const int wr = wid & 1, wc = wid >> 1;           // 2 x 4 warp grid
    const int bx = blockIdx.x, rb = bx >> 2, nb = bx & 3;

    float acc[4][8][4];
#pragma unroll
    for (int mi = 0; mi < 4; mi++)
#pragma unroll
        for (int ni = 0; ni < 8; ni++)
#pragma unroll
            for (int j = 0; j < 4; j++) acc[mi][ni][j] = 0.f;

    // cp.async staging: A 1024 + B 2048 16B-ops = 12/thread
    auto issue = [&](int c, int buf) {
        int kk = c * 64;
        const char* Ab = (const char*)(g_h_hi + (size_t)rb * 128 * Hh + kk);
        const char* Bp = (const char*)(g_w_hi + (size_t)nb * 256 * Hh + kk);
        const uint32_t sA = sb + buf * BUF_B;
        const uint32_t sB = sA + A_TILE;
#pragma unroll
        for (int t = 0; t < 4; t++) {
            int i = tid + t * 256, r = i >> 3, v = i & 7;
            CPA16(sA + r * (SROW * 2) + v * 16, Ab + (size_t)r * (Hh * 2) + v * 16);
        }
#pragma unroll
        for (int t = 0; t < 8; t++) {
            int i = tid + t * 256, n = i >> 3, v = i & 7;
            CPA16(sB + n * (SROW * 2) + v * 16, Bp + (size_t)n * (Hh * 2) + v * 16);
        }
    };

    // ldmatrix lane-address components (hardware-verified rounds 10/11/14)
    const int a_row = wr * 64 + (lane & 15);                       // + mi*16
    const int a_kof = ((lane >> 4) << 4);
    const int b_row = wc * 64 + ((lane >> 4) << 3) + (lane & 7);   // + p*16
    const int b_kof = (((lane >> 3) & 1) << 4);

    issue(0, 0); CP_COMMIT();
    issue(1, 1); CP_COMMIT();

    for (int c = 0; c < 10; c++) {
        const int buf = c & 1;
        if (c < 8) { CP_WAIT(1); } else { CP_WAIT(0); }
        __syncthreads();

        const uint32_t sA = sb + buf * BUF_B;
        const uint32_t sB = sA + A_TILE;
#pragma unroll
        for (int ks = 0; ks < 4; ks++) {
            uint32_t bf[4][4];
#pragma unroll
            for (int p = 0; p < 4; p++) {
                uint32_t bd = sB + (b_row + p * 16) * (SROW * 2) + ks * 32 + b_kof;
                LDMX4(bf[p][0], bf[p][1], bf[p][2], bf[p][3], bd);
            }
            uint32_t ah[4][4];
#pragma unroll
            for (int mi = 0; mi < 4; mi++) {
                uint32_t r0 = (a_row + mi * 16) * (SROW * 2) + ks * 32 + a_kof;
                LDMX4(ah[mi][0], ah[mi][1], ah[mi][2], ah[mi][3], sA + r0);
            }
#pragma unroll
            for (int mi = 0; mi < 4; mi++)
#pragma unroll
                for (int ni = 0; ni < 8; ni++) {
                    uint32_t b0 = bf[ni >> 1][(ni & 1) * 2 + 0];
                    uint32_t b1 = bf[ni >> 1][(ni & 1) * 2 + 1];
                    MMA16816(acc[mi][ni], ah[mi], b0, b1);
                }
        }
        if (c + 2 < 10) {
            __syncthreads();            // all warps done reading buf
            issue(c + 2, buf); CP_COMMIT();
        }
    }

    // Epilogue: raw logits (verified mapping; rows +8 for d2,d3)
    const int mb = rb * 128 + wr * 64 + (lane >> 2);
    const int cb = nb * 256 + wc * 64 + 2 * (lane & 3);
#pragma unroll
    for (int mi = 0; mi < 4; mi++)
#pragma unroll
        for (int ni = 0; ni < 8; ni++) {
            int m = mb + mi * 16;
            int cc = cb + ni * 8;
            *(float2*)(out + (size_t)m * Vv + cc) =
                make_float2(acc[mi][ni][0], acc[mi][ni][1]);
            *(float2*)(out + (size_t)(m + 8) * Vv + cc) =
                make_float2(acc[mi][ni][2], acc[mi][ni][3]);
        }
}

// ---------------------------------------------------------------------------
// Kernel 5: in-place out = log_softmax(raw + b2). One warp per row.
// ---------------------------------------------------------------------------
__global__ __launch_bounds__(256) void fixup_kernel(
    float* __restrict__ out, const float* __restrict__ b2) {
    const int row = blockIdx.x * 8 + (threadIdx.x >> 5);
    const int lane = threadIdx.x & 31;
    float4* orow = (float4*)(out + (size_t)row * Vv);
    const float4* b4 = (const float4*)b2;

    float4 v[8];
    float mx = -INFINITY;
#pragma unroll
    for (int j = 0; j < 8; j++) {
        int f = lane + j * 32;
        float4 t = orow[f];
        float4 bbv = b4[f];
        t.x += bbv.x; t.y += bbv.y; t.z += bbv.z; t.w += bbv.w;
        v[j] = t;
        mx = fmaxf(mx, fmaxf(fmaxf(t.x, t.y), fmaxf(t.z, t.w)));
    }
#pragma unroll
    for (int s = 16; s > 0; s >>= 1) mx = fmaxf(mx, __shfl_xor_sync(0xffffffffu, mx, s));
    float sum = 0.f;
#pragma unroll
    for (int j = 0; j < 8; j++)
        sum += __expf(v[j].x - mx) + __expf(v[j].y - mx)
             + __expf(v[j].z - mx) + __expf(v[j].w - mx);
#pragma unroll
    for (int s = 16; s > 0; s >>= 1) sum += __shfl_xor_sync(0xffffffffu, sum, s);
    float lz = mx + __logf(sum);
#pragma unroll
    for (int j = 0; j < 8; j++) {
        float4 t = v[j];
        t.x -= lz; t.y -= lz; t.z -= lz; t.w -= lz;
        orow[lane + j * 32] = t;
    }
}

// ---------------------------------------------------------------------------
__global__ void tail_kernel(const int* __restrict__ sl, const int* __restrict__ tl,
                            float* __restrict__ out, long long base, int tail) {
    int i = threadIdx.x;
    if (i < tail && i < 8) {
        out[base + i] = (i < 4) ? (float)sl[i] : (float)tl[i - 4];
    }
}

extern "C" void kernel_launch(void* const* d_in, const int* in_sizes, int n_in,
                              void* d_out, int out_size) {
    const float* src = (const float*)d_in[0];
    const int*   sl  = (const int*)d_in[1];
    const float* tgt = (const float*)d_in[2];
    const int*   tl  = (const int*)d_in[3];
    const float* W1  = (const float*)d_in[4];
    const float* b1  = (const float*)d_in[5];
    const float* W2  = (const float*)d_in[6];
    const float* b2  = (const float*)d_in[7];
    float* out = (float*)d_out;

    cudaFuncSetAttribute(gemm_kernel,
                         cudaFuncAttributeMaxDynamicSharedMemorySize, GEMM_SMEM);

    proj_kernel<<<480, 256>>>(src, tgt, W1, b1);       // 96 row-blocks x 5
    w2split_kernel<<<(Hh * Vv) / 256, 256>>>(W2);      // 2560 CTAs
    h_build_kernel<<<RR / 8, 256>>>();                 // 4096 CTAs
    gemm_kernel<<<1024, 256, GEMM_SMEM>>>(out);        // 256 rb x 4 nb
    fixup_kernel<<<RR / 8, 256>>>(out, b2);

    long long mainN = (long long)RR * Vv;              // 33554432
    long long tail = (long long)out_size - mainN;
    if (tail > 0) tail_kernel<<<1, 32>>>(sl, tl, out, mainN, (int)tail);
}

// round 17
// speedup vs baseline: 4.6260x; 1.0063x over previous
#include <cuda_runtime.h>
#include <cuda_bf16.h>
#include <math.h>
#include <stdint.h>

#define Bb 4
#define Tt 128
#define Uu 64
#define Dd 512
#define Hh 640
#define Vv 1024
#define RR (Bb*Tt*Uu)          // 32768 joint rows

// ---------------- scratch (device globals; no allocs allowed) --------------
__device__ float g_ps[Bb*Tt*Hh];
__device__ float g_pt[Bb*Uu*Hh];
__device__ __align__(16) __nv_bfloat16 g_h_hi[(size_t)RR*Hh];   // 40 MB
__device__ __align__(16) __nv_bfloat16 g_w_hi[(size_t)Vv*Hh];   // W2^T bf16 [V][K]

static __device__ __forceinline__ uint32_t s2u(const void* p){
    uint32_t a;
    asm("{ .reg .u64 t; cvta.to.shared.u64 t, %1; cvt.u32.u64 %0, t; }"
        : "=r"(a) : "l"(p));
    return a;
}
#define LDMX4(r0,r1,r2,r3,addr) \
    asm volatile("ldmatrix.sync.aligned.m8n8.x4.shared.b16 {%0,%1,%2,%3}, [%4];" \
        : "=r"(r0),"=r"(r1),"=r"(r2),"=r"(r3) : "r"(addr))
#define MMA16816(d,a,b0,b1) \
    asm volatile("mma.sync.aligned.m16n8k16.row.col.f32.bf16.bf16.f32 " \
        "{%0,%1,%2,%3}, {%4,%5,%6,%7}, {%8,%9}, {%0,%1,%2,%3};" \
        : "+f"((d)[0]),"+f"((d)[1]),"+f"((d)[2]),"+f"((d)[3]) \
        : "r"((a)[0]),"r"((a)[1]),"r"((a)[2]),"r"((a)[3]), "r"(b0),"r"(b1))
#define CPA16(dst, src) \
    asm volatile("cp.async.cg.shared.global [%0], [%1], 16;" \
        :: "r"(dst), "l"(__cvta_generic_to_global(src)) : "memory")
#define CP_COMMIT() asm volatile("cp.async.commit_group;" ::: "memory")
#define CP_WAIT(n)  asm volatile("cp.async.wait_group %0;" :: "n"(n) : "memory")

// ---------------------------------------------------------------------------
// Kernel 1: proj. 480 CTAs = 96 row-blocks x 5 col-chunks of 128.
// unroll 8 -> deeper LDG MLP (loop is L2-latency bound).
// ---------------------------------------------------------------------------
__global__ __launch_bounds__(256) void proj_kernel(
    const float* __restrict__ src, const float* __restrict__ tgt,
    const float* __restrict__ W1, const float* __restrict__ b1) {
    __shared__ float s_in[8 * Dd];
    const int bx = blockIdx.x;
    const int rb = bx / 5, chunk = bx - rb * 5;
    const int row0 = rb * 8;
    const bool is_src = (row0 < Bb * Tt);
    const float* inp = is_src ? src + (size_t)row0 * Dd
                              : tgt + (size_t)(row0 - Bb * Tt) * Dd;
    const float* w = W1 + (is_src ? 0 : (size_t)Dd * Hh);
    float* outp = is_src ? g_ps + (size_t)row0 * Hh
                         : g_pt + (size_t)(row0 - Bb * Tt) * Hh;
    const int tid = threadIdx.x;
    for (int i = tid; i < 8 * Dd; i += 256) s_in[i] = inp[i];
    __syncthreads();

    const int c = chunk * 128 + (tid & 127);
    const int rbase = (tid >> 7) * 4;
    float a0 = 0.f, a1 = 0.f, a2 = 0.f, a3 = 0.f;
#pragma unroll 8
    for (int d = 0; d < Dd; d++) {
        float wv = w[(size_t)d * Hh + c];
        a0 = fmaf(s_in[(rbase + 0) * Dd + d], wv, a0);
        a1 = fmaf(s_in[(rbase + 1) * Dd + d], wv, a1);
        a2 = fmaf(s_in[(rbase + 2) * Dd + d], wv, a2);
        a3 = fmaf(s_in[(rbase + 3) * Dd + d], wv, a3);
    }
    float bb = is_src ? b1[c] : 0.f;
    outp[(size_t)(rbase + 0) * Hh + c] = a0 + bb;
    outp[(size_t)(rbase + 1) * Hh + c] = a1 + bb;
    outp[(size_t)(rbase + 2) * Hh + c] = a2 + bb;
    outp[(size_t)(rbase + 3) * Hh + c] = a3 + bb;
}

// ---------------------------------------------------------------------------
// Kernel 2: W2 -> bf16 transpose, [V][K] K-major.
// ---------------------------------------------------------------------------
__global__ __launch_bounds__(256) void w2split_kernel(const float* __restrict__ W2) {
    int idx = blockIdx.x * 256 + threadIdx.x;   // = k*Vv + n
    int k = idx >> 10, n = idx & 1023;
    g_w_hi[(size_t)n * Hh + k] = __float2bfloat16(W2[idx]);
}

// ---------------------------------------------------------------------------
// Kernel 3: h = tanh(ps+pt) -> bf16. One warp per row, 8 rows/CTA.
// ---------------------------------------------------------------------------
__global__ __launch_bounds__(256) void h_build_kernel() {
    const int row = blockIdx.x * 8 + (threadIdx.x >> 5);
    const int lane = threadIdx.x & 31;
    const float* psr = g_ps + (size_t)(row >> 6) * Hh;
    const float* ptr = g_pt + (size_t)(((row >> 13) << 6) + (row & 63)) * Hh;
    __nv_bfloat16* hh = g_h_hi + (size_t)row * Hh;
#pragma unroll 5
    for (int j = 0; j < 20; j++) {
        int k = lane + j * 32;
        float x = psr[k] + ptr[k];
        float e; asm("ex2.approx.f32 %0, %1;" : "=f"(e) : "f"(x * 2.8853900817779268f));
        float r; asm("rcp.approx.f32 %0, %1;" : "=f"(r) : "f"(e + 1.0f));
        hh[k] = __float2bfloat16(fmaf(-2.0f, r, 1.0f));
    }
}

// ---------------------------------------------------------------------------
// Kernel 4: single bf16 GEMM, mma.sync m16n8k16. K = 640 (10 chunks of 64).
// CTA tile 128 rows x 256 cols; grid 1024 (rb = bx>>2, nb = bx&3).
// 8 warps = 2 row-groups x 4 col-groups; warp tile 64x64.
// TRIPLE-buffered cp.async: one __syncthreads per chunk (the pre-issue
// barrier is redundant with 3 buffers: buffer (c+2)%3 was last read by
// chunk c-1, and every warp finished chunk c-1 before the top-of-iter-c
// barrier). Prefetch issued BEFORE compute for wider copy/MMA overlap.
// smem rows padded to 72 elems -> conflict-free ldmatrix.
// ---------------------------------------------------------------------------
#define SROW 72
#define A_TILE (128 * SROW * 2)            // 18432 B
#define B_TILE (256 * SROW * 2)            // 36864 B
#define BUF_B  (A_TILE + B_TILE)           // 55296 B
#define GEMM_SMEM (3 * BUF_B)              // 165888 B

__global__ __launch_bounds__(256) void gemm_kernel(float* __restrict__ out) {
    extern __shared__ __align__(16) char smem[];
    const uint32_t sb = s2u(smem);
    const int tid = threadIdx.x;
    const int wid = tid >> 5, lane = tid & 31;
    const int wr = wid & 1, wc = wid >> 1;           // 2 x 4 warp grid
    const int bx = blockIdx.x, rb = bx >> 2, nb = bx & 3;

    float acc[4][8][4];
#pragma unroll
    for (int mi = 0; mi < 4; mi++)
#pragma unroll
        for (int ni = 0; ni < 8; ni++)
#pragma unroll
            for (int j = 0; j < 4; j++) acc[mi][ni][j] = 0.f;

    // cp.async staging: A 1024 + B 2048 16B-ops = 12/thread
    auto issue = [&](int c, int buf) {
        int kk = c * 64;
        const char* Ab = (const char*)(g_h_hi + (size_t)rb * 128 * Hh + kk);
        const char* Bp = (const char*)(g_w_hi + (size_t)nb * 256 * Hh + kk);
        const uint32_t sA = sb + buf * BUF_B;
        const uint32_t sB = sA + A_TILE;
#pragma unroll
        for (int t = 0; t < 4; t++) {
            int i = tid + t * 256, r = i >> 3, v = i & 7;
            CPA16(sA + r * (SROW * 2) + v * 16, Ab + (size_t)r * (Hh * 2) + v * 16);
        }
#pragma unroll
        for (int t = 0; t < 8; t++) {
            int i = tid + t * 256, n = i >> 3, v = i & 7;
            CPA16(sB + n * (SROW * 2) + v * 16, Bp + (size_t)n * (Hh * 2) + v * 16);
        }
    };

    // ldmatrix lane-address components (hardware-verified rounds 10/11/14/16)
    const int a_row = wr * 64 + (lane & 15);                       // + mi*16
    const int a_kof = ((lane >> 4) << 4);
    const int b_row = wc * 64 + ((lane >> 4) << 3) + (lane & 7);   // + p*16
    const int b_kof = (((lane >> 3) & 1) << 4);

    issue(0, 0); CP_COMMIT();
    issue(1, 1); CP_COMMIT();

    for (int c = 0; c < 10; c++) {
        const int buf = c % 3;
        if (c < 8) { CP_WAIT(1); } else { CP_WAIT(0); }
        __syncthreads();                    // chunk c visible to all warps

        if (c + 2 < 10) {                   // prefetch BEFORE compute;
            issue(c + 2, (c + 2) % 3);      // target buf last read by c-1,
            CP_COMMIT();                    // whose compute preceded the sync
        }

        const uint32_t sA = sb + buf * BUF_B;
        const uint32_t sB = sA + A_TILE;
#pragma unroll
        for (int ks = 0; ks < 4; ks++) {
            uint32_t bf[4][4];
#pragma unroll
            for (int p = 0; p < 4; p++) {
                uint32_t bd = sB + (b_row + p * 16) * (SROW * 2) + ks * 32 + b_kof;
                LDMX4(bf[p][0], bf[p][1], bf[p][2], bf[p][3], bd);
            }
            uint32_t ah[4][4];
#pragma unroll
            for (int mi = 0; mi < 4; mi++) {
                uint32_t r0 = (a_row + mi * 16) * (SROW * 2) + ks * 32 + a_kof;
                LDMX4(ah[mi][0], ah[mi][1], ah[mi][2], ah[mi][3], sA + r0);
            }
#pragma unroll
            for (int mi = 0; mi < 4; mi++)
#pragma unroll
                for (int ni = 0; ni < 8; ni++) {
                    uint32_t b0 = bf[ni >> 1][(ni & 1) * 2 + 0];
                    uint32_t b1 = bf[ni >> 1][(ni & 1) * 2 + 1];
                    MMA16816(acc[mi][ni], ah[mi], b0, b1);
                }
        }
    }

    // Epilogue: raw logits (verified mapping; rows +8 for d2,d3)
    const int mb = rb * 128 + wr * 64 + (lane >> 2);
    const int cb = nb * 256 + wc * 64 + 2 * (lane & 3);
#pragma unroll
    for (int mi = 0; mi < 4; mi++)
#pragma unroll
        for (int ni = 0; ni < 8; ni++) {
            int m = mb + mi * 16;
            int cc = cb + ni * 8;
            *(float2*)(out + (size_t)m * Vv + cc) =
                make_float2(acc[mi][ni][0], acc[mi][ni][1]);
            *(float2*)(out + (size_t)(m + 8) * Vv + cc) =
                make_float2(acc[mi][ni][2], acc[mi][ni][3]);
        }
}

// ---------------------------------------------------------------------------
// Kernel 5: in-place out = log_softmax(raw + b2). One warp per row.
// ---------------------------------------------------------------------------
__global__ __launch_bounds__(256) void fixup_kernel(
    float* __restrict__ out, const float* __restrict__ b2) {
    const int row = blockIdx.x * 8 + (threadIdx.x >> 5);
    const int lane = threadIdx.x & 31;
    float4* orow = (float4*)(out + (size_t)row * Vv);
    const float4* b4 = (const float4*)b2;

    float4 v[8];
    float mx = -INFINITY;
#pragma unroll
    for (int j = 0; j < 8; j++) {
        int f = lane + j * 32;
        float4 t = orow[f];
        float4 bbv = b4[f];
        t.x += bbv.x; t.y += bbv.y; t.z += bbv.z; t.w += bbv.w;
        v[j] = t;
        mx = fmaxf(mx, fmaxf(fmaxf(t.x, t.y), fmaxf(t.z, t.w)));
    }
#pragma unroll
    for (int s = 16; s > 0; s >>= 1) mx = fmaxf(mx, __shfl_xor_sync(0xffffffffu, mx, s));
    float sum = 0.f;
#pragma unroll
    for (int j = 0; j < 8; j++)
        sum += __expf(v[j].x - mx) + __expf(v[j].y - mx)
             + __expf(v[j].z - mx) + __expf(v[j].w - mx);
#pragma unroll
    for (int s = 16; s > 0; s >>= 1) sum += __shfl_xor_sync(0xffffffffu, sum, s);
    float lz = mx + __logf(sum);
#pragma unroll
    for (int j = 0; j < 8; j++) {
        float4 t = v[j];
        t.x -= lz; t.y -= lz; t.z -= lz; t.w -= lz;
        orow[lane + j * 32] = t;
    }
}

// ---------------------------------------------------------------------------
__global__ void tail_kernel(const int* __restrict__ sl, const int* __restrict__ tl,
                            float* __restrict__ out, long long base, int tail) {
    int i = threadIdx.x;
    if (i < tail && i < 8) {
        out[base + i] = (i < 4) ? (float)sl[i] : (float)tl[i - 4];
    }
}

extern "C" void kernel_launch(void* const* d_in, const int* in_sizes, int n_in,
                              void* d_out, int out_size) {
    const float* src = (const float*)d_in[0];
    const int*   sl  = (const int*)d_in[1];
    const float* tgt = (const float*)d_in[2];
    const int*   tl  = (const int*)d_in[3];
    const float* W1  = (const float*)d_in[4];
    const float* b1  = (const float*)d_in[5];
    const float* W2  = (const float*)d_in[6];
    const float* b2  = (const float*)d_in[7];
    float* out = (float*)d_out;

    cudaFuncSetAttribute(gemm_kernel,
                         cudaFuncAttributeMaxDynamicSharedMemorySize, GEMM_SMEM);

    proj_kernel<<<480, 256>>>(src, tgt, W1, b1);       // 96 row-blocks x 5
    w2split_kernel<<<(Hh * Vv) / 256, 256>>>(W2);      // 2560 CTAs
    h_build_kernel<<<RR / 8, 256>>>();                 // 4096 CTAs
    gemm_kernel<<<1024, 256, GEMM_SMEM>>>(out);        // 256 rb x 4 nb
    fixup_kernel<<<RR / 8, 256>>>(out, b2);

    long long mainN = (long long)RR * Vv;              // 33554432
    long long tail = (long long)out_size - mainN;
    if (tail > 0) tail_kernel<<<1, 32>>>(sl, tl, out, mainN, (int)tail);
}